// round 4
// baseline (speedup 1.0000x reference)
#include <cuda_runtime.h>
#include <cuda_fp16.h>

#define N_MAX   100000
#define E_MAX   1600000
#define NFEAT   128
#define NHID    64
#define NCLS    40

// ---------------- device scratch (allocation-free) ----------------
__device__ int   g_is64;
__device__ int   g_src[E_MAX];
__device__ int   g_dst[E_MAX];
__device__ int   g_csr[E_MAX];
__device__ int   g_deg[N_MAX];
__device__ int   g_off[N_MAX];
__device__ int   g_cur[N_MAX];
__device__ unsigned long long g_part[512];   // lookback: (valid<<32)|sum
__device__ unsigned g_h1h[N_MAX * 32];   // h1 [N,64] fp16 (2 feats / word)
__device__ unsigned g_r1 [N_MAX * 32];   // relu(agg1/cnt) [N,64] fp16
__device__ unsigned g_h2h[N_MAX * 20];   // h2 [N,40] fp16

// ---------------- pre: zero deg + lookback flags + dtype detect -----
__global__ void k_pre(const unsigned* __restrict__ ei, int n) {
    int i = blockIdx.x * blockDim.x + threadIdx.x;
    if (i < n) g_deg[i] = 0;
    if (i < 512) g_part[i] = 0ULL;
    if (i == 0) {
        unsigned hi = 0;
        #pragma unroll
        for (int j = 1; j < 64; j += 2) hi |= ei[j];
        g_is64 = (hi == 0u) ? 1 : 0;
    }
}

// ---------------- hist: edges -> int32 + degree histogram ----------
__global__ void k_hist(const void* __restrict__ ei, int E) {
    int i = blockIdx.x * blockDim.x + threadIdx.x;
    if (i >= E) return;
    int s, d;
    if (g_is64) {
        const long long* p = (const long long*)ei;
        s = (int)p[i]; d = (int)p[E + i];
    } else {
        const int* p = (const int*)ei;
        s = p[i]; d = p[E + i];
    }
    g_src[i] = s;
    g_dst[i] = d;
    atomicAdd(&g_deg[d], 1);
}

// ------- scan: single-pass exclusive scan of deg (decoupled lookback)
__global__ __launch_bounds__(256) void k_scan(int n) {
    int b = blockIdx.x;
    int i = b * 256 + threadIdx.x;
    int v = (i < n) ? g_deg[i] : 0;
    int lane = threadIdx.x & 31, w = threadIdx.x >> 5;

    // block-local inclusive scan
    int s = v;
    #pragma unroll
    for (int o = 1; o < 32; o <<= 1) {
        int t = __shfl_up_sync(0xFFFFFFFFu, s, o);
        if (lane >= o) s += t;
    }
    __shared__ int wsum[8];
    __shared__ int s_prev;
    if (lane == 31) wsum[w] = s;
    __syncthreads();
    if (w == 0) {
        int t = (lane < 8) ? wsum[lane] : 0;
        #pragma unroll
        for (int o = 1; o < 8; o <<= 1) {
            int u = __shfl_up_sync(0xFFFFFFFFu, t, o);
            if (lane >= o) t += u;
        }
        if (lane < 8) wsum[lane] = t;
    }
    __syncthreads();
    int incl = s + (w > 0 ? wsum[w - 1] : 0);

    // publish this block's aggregate ASAP
    if (threadIdx.x == 255)
        atomicExch(&g_part[b], (1ULL << 32) | (unsigned)incl);

    // warp 0: sum aggregates of all predecessor blocks
    if (threadIdx.x < 32) {
        int sum = 0;
        for (int p = b - 1 - lane; p >= 0; p -= 32) {
            unsigned long long pk;
            volatile unsigned long long* pp = &g_part[p];
            do { pk = *pp; } while (!(pk >> 32));
            sum += (int)(unsigned)pk;
        }
        #pragma unroll
        for (int o = 16; o > 0; o >>= 1)
            sum += __shfl_xor_sync(0xFFFFFFFFu, sum, o);
        if (threadIdx.x == 0) s_prev = sum;
    }
    __syncthreads();

    if (i < n) {
        int off = s_prev + incl - v;
        g_off[i] = off;
        g_cur[i] = off;
    }
}

// ---------------- csr: scatter src ids into CSR order ----------------
__global__ void k_csr(int E) {
    int i = blockIdx.x * blockDim.x + threadIdx.x;
    if (i >= E) return;
    int d = g_dst[i];
    int pos = atomicAdd(&g_cur[d], 1);
    g_csr[pos] = g_src[i];
}

// ---------------- GEMM1: h1 = x @ W1^T + b1 -> [N,64] fp16 -----------
__global__ __launch_bounds__(256) void k_gemm1(
    const float* __restrict__ x, const float* __restrict__ W,
    const float* __restrict__ b, int n)
{
    __shared__ __align__(16) float xs[64][68];
    __shared__ __align__(16) float ws[64][68];
    int tid  = threadIdx.x;
    int row0 = blockIdx.x * 64;
    int tx = tid & 15, ty = tid >> 4;

    float acc[4][4];
    #pragma unroll
    for (int i = 0; i < 4; ++i)
        #pragma unroll
        for (int j = 0; j < 4; ++j) acc[i][j] = 0.f;

    for (int kk = 0; kk < NFEAT; kk += 64) {
        #pragma unroll
        for (int it = 0; it < 4; ++it) {
            int idx = tid + it * 256;
            int r = idx >> 4, k4 = idx & 15;
            float4 v = make_float4(0.f, 0.f, 0.f, 0.f);
            int row = row0 + r;
            if (row < n)
                v = __ldg((const float4*)(x + (size_t)row * NFEAT + kk) + k4);
            xs[k4 * 4 + 0][r] = v.x; xs[k4 * 4 + 1][r] = v.y;
            xs[k4 * 4 + 2][r] = v.z; xs[k4 * 4 + 3][r] = v.w;
        }
        #pragma unroll
        for (int it = 0; it < 4; ++it) {
            int idx = tid + it * 256;
            int c = idx >> 4, k4 = idx & 15;
            float4 v = __ldg((const float4*)(W + (size_t)c * NFEAT + kk) + k4);
            ws[k4 * 4 + 0][c] = v.x; ws[k4 * 4 + 1][c] = v.y;
            ws[k4 * 4 + 2][c] = v.z; ws[k4 * 4 + 3][c] = v.w;
        }
        __syncthreads();
        #pragma unroll
        for (int k = 0; k < 64; ++k) {
            float4 xv = *(const float4*)&xs[k][ty * 4];
            float4 wv = *(const float4*)&ws[k][tx * 4];
            float ax[4] = {xv.x, xv.y, xv.z, xv.w};
            float aw[4] = {wv.x, wv.y, wv.z, wv.w};
            #pragma unroll
            for (int i = 0; i < 4; ++i)
                #pragma unroll
                for (int j = 0; j < 4; ++j) acc[i][j] += ax[i] * aw[j];
        }
        __syncthreads();
    }

    float4 bb = __ldg((const float4*)b + tx);
    #pragma unroll
    for (int i = 0; i < 4; ++i) {
        int row = row0 + ty * 4 + i;
        if (row < n) {
            __half2 p0 = __floats2half2_rn(acc[i][0] + bb.x, acc[i][1] + bb.y);
            __half2 p1 = __floats2half2_rn(acc[i][2] + bb.z, acc[i][3] + bb.w);
            uint2 o;
            o.x = *(unsigned*)&p0; o.y = *(unsigned*)&p1;
            ((uint2*)g_h1h)[row * 16 + tx] = o;
        }
    }
}

// ---- agg1: r1 = relu((h1[row] + sum h1[csr]) / (deg+1)) -------------
// warp/row; lane owns 2 features (one 32-bit word); shfl-broadcast idx;
// inner loop unrolled x4 for MLP; fp32 accumulation, no reduction epilogue
__global__ __launch_bounds__(256) void k_agg1(int n) {
    int row = (blockIdx.x * 256 + threadIdx.x) >> 5;
    if (row >= n) return;
    int lane = threadIdx.x & 31;
    int start = g_off[row], deg = g_deg[row], end = start + deg;

    float ax = 0.f, ay = 0.f;
    for (int base = start; base < end; base += 32) {
        int cnt = min(32, end - base);
        int idx = 0;
        if (base + lane < end) idx = __ldg(&g_csr[base + lane]);
        int jj = 0;
        for (; jj + 4 <= cnt; jj += 4) {
            int s0 = __shfl_sync(0xFFFFFFFFu, idx, jj);
            int s1 = __shfl_sync(0xFFFFFFFFu, idx, jj + 1);
            int s2 = __shfl_sync(0xFFFFFFFFu, idx, jj + 2);
            int s3 = __shfl_sync(0xFFFFFFFFu, idx, jj + 3);
            unsigned v0 = __ldg(&g_h1h[s0 * 32 + lane]);
            unsigned v1 = __ldg(&g_h1h[s1 * 32 + lane]);
            unsigned v2 = __ldg(&g_h1h[s2 * 32 + lane]);
            unsigned v3 = __ldg(&g_h1h[s3 * 32 + lane]);
            float2 f0 = __half22float2(*(__half2*)&v0);
            float2 f1 = __half22float2(*(__half2*)&v1);
            float2 f2 = __half22float2(*(__half2*)&v2);
            float2 f3 = __half22float2(*(__half2*)&v3);
            ax += (f0.x + f1.x) + (f2.x + f3.x);
            ay += (f0.y + f1.y) + (f2.y + f3.y);
        }
        for (; jj < cnt; ++jj) {
            int s0 = __shfl_sync(0xFFFFFFFFu, idx, jj);
            unsigned v0 = __ldg(&g_h1h[s0 * 32 + lane]);
            float2 f0 = __half22float2(*(__half2*)&v0);
            ax += f0.x; ay += f0.y;
        }
    }
    // self-loop + mean + relu
    unsigned vs = g_h1h[row * 32 + lane];
    float2 fs = __half22float2(*(__half2*)&vs);
    float inv = 1.0f / (float)(deg + 1);
    float r0 = fmaxf((ax + fs.x) * inv, 0.f);
    float r1 = fmaxf((ay + fs.y) * inv, 0.f);
    __half2 p = __floats2half2_rn(r0, r1);
    g_r1[row * 32 + lane] = *(unsigned*)&p;
}

// ---------------- GEMM2: h2 = r1 @ W2^T + b2 -> [N,40] fp16 ----------
__global__ __launch_bounds__(160) void k_gemm2(
    const float* __restrict__ W, const float* __restrict__ b, int n)
{
    __shared__ __align__(16) float rs[64][68];
    __shared__ __align__(16) float ws[64][44];
    int tid  = threadIdx.x;
    int row0 = blockIdx.x * 64;

    for (int idx = tid; idx < 1024; idx += 160) {
        int r = idx >> 4, k4 = idx & 15;
        int row = row0 + r;
        float4 v = make_float4(0.f, 0.f, 0.f, 0.f);
        if (row < n) {
            uint2 a = ((const uint2*)g_r1)[row * 16 + k4];
            float2 f0 = __half22float2(*(__half2*)&a.x);
            float2 f1 = __half22float2(*(__half2*)&a.y);
            v.x = f0.x; v.y = f0.y; v.z = f1.x; v.w = f1.y;
        }
        rs[k4 * 4 + 0][r] = v.x; rs[k4 * 4 + 1][r] = v.y;
        rs[k4 * 4 + 2][r] = v.z; rs[k4 * 4 + 3][r] = v.w;
    }
    for (int idx = tid; idx < 640; idx += 160) {
        int c = idx >> 4, k4 = idx & 15;
        float4 v = __ldg((const float4*)(W + (size_t)c * NHID) + k4);
        ws[k4 * 4 + 0][c] = v.x; ws[k4 * 4 + 1][c] = v.y;
        ws[k4 * 4 + 2][c] = v.z; ws[k4 * 4 + 3][c] = v.w;
    }
    __syncthreads();

    int tx = tid % 10, ty = tid / 10;
    float acc[4][4];
    #pragma unroll
    for (int i = 0; i < 4; ++i)
        #pragma unroll
        for (int j = 0; j < 4; ++j) acc[i][j] = 0.f;

    #pragma unroll
    for (int k = 0; k < 64; ++k) {
        float4 xv = *(const float4*)&rs[k][ty * 4];
        float4 wv = *(const float4*)&ws[k][tx * 4];
        float a0[4] = {xv.x, xv.y, xv.z, xv.w};
        float a1[4] = {wv.x, wv.y, wv.z, wv.w};
        #pragma unroll
        for (int i = 0; i < 4; ++i)
            #pragma unroll
            for (int j = 0; j < 4; ++j) acc[i][j] += a0[i] * a1[j];
    }

    float4 bb = __ldg((const float4*)b + tx);
    #pragma unroll
    for (int i = 0; i < 4; ++i) {
        int row = row0 + ty * 4 + i;
        if (row < n) {
            __half2 p0 = __floats2half2_rn(acc[i][0] + bb.x, acc[i][1] + bb.y);
            __half2 p1 = __floats2half2_rn(acc[i][2] + bb.z, acc[i][3] + bb.w);
            uint2 o;
            o.x = *(unsigned*)&p0; o.y = *(unsigned*)&p1;
            ((uint2*)g_h2h)[row * 10 + tx] = o;
        }
    }
}

// ---- agg2 + log_softmax: out = lsm((h2[row] + sum h2[csr])/(deg+1)) --
// warp/row; lanes 0..19 own 2 of 40 features; shfl-broadcast idx
__global__ __launch_bounds__(256) void k_agg2(float* __restrict__ out, int n) {
    int row = (blockIdx.x * 256 + threadIdx.x) >> 5;
    if (row >= n) return;
    int lane = threadIdx.x & 31;
    int start = g_off[row], deg = g_deg[row], end = start + deg;
    bool act = (lane < 20);
    int fofs = act ? lane : 0;

    float ax = 0.f, ay = 0.f;
    for (int base = start; base < end; base += 32) {
        int cnt = min(32, end - base);
        int idx = 0;
        if (base + lane < end) idx = __ldg(&g_csr[base + lane]);
        int jj = 0;
        for (; jj + 4 <= cnt; jj += 4) {
            int s0 = __shfl_sync(0xFFFFFFFFu, idx, jj);
            int s1 = __shfl_sync(0xFFFFFFFFu, idx, jj + 1);
            int s2 = __shfl_sync(0xFFFFFFFFu, idx, jj + 2);
            int s3 = __shfl_sync(0xFFFFFFFFu, idx, jj + 3);
            if (act) {
                unsigned v0 = __ldg(&g_h2h[s0 * 20 + fofs]);
                unsigned v1 = __ldg(&g_h2h[s1 * 20 + fofs]);
                unsigned v2 = __ldg(&g_h2h[s2 * 20 + fofs]);
                unsigned v3 = __ldg(&g_h2h[s3 * 20 + fofs]);
                float2 f0 = __half22float2(*(__half2*)&v0);
                float2 f1 = __half22float2(*(__half2*)&v1);
                float2 f2 = __half22float2(*(__half2*)&v2);
                float2 f3 = __half22float2(*(__half2*)&v3);
                ax += (f0.x + f1.x) + (f2.x + f3.x);
                ay += (f0.y + f1.y) + (f2.y + f3.y);
            }
        }
        for (; jj < cnt; ++jj) {
            int s0 = __shfl_sync(0xFFFFFFFFu, idx, jj);
            if (act) {
                unsigned v0 = __ldg(&g_h2h[s0 * 20 + fofs]);
                float2 f0 = __half22float2(*(__half2*)&v0);
                ax += f0.x; ay += f0.y;
            }
        }
    }

    float x0 = -3.4e38f, x1 = -3.4e38f;
    float inv = 1.0f / (float)(deg + 1);
    if (act) {
        unsigned vs = g_h2h[row * 20 + fofs];
        float2 fs = __half22float2(*(__half2*)&vs);
        x0 = (ax + fs.x) * inv;
        x1 = (ay + fs.y) * inv;
    }
    float m = fmaxf(x0, x1);
    #pragma unroll
    for (int o = 16; o > 0; o >>= 1)
        m = fmaxf(m, __shfl_xor_sync(0xFFFFFFFFu, m, o));
    float s = act ? (expf(x0 - m) + expf(x1 - m)) : 0.f;
    #pragma unroll
    for (int o = 16; o > 0; o >>= 1)
        s += __shfl_xor_sync(0xFFFFFFFFu, s, o);
    float l = m + logf(s);
    if (act) {
        float2 o2;
        o2.x = x0 - l; o2.y = x1 - l;
        ((float2*)(out + (size_t)row * NCLS))[lane] = o2;
    }
}

// ---------------- launch ----------------
extern "C" void kernel_launch(void* const* d_in, const int* in_sizes, int n_in,
                              void* d_out, int out_size)
{
    const float* x  = (const float*)d_in[0];
    const void*  ei = d_in[1];
    const float* W1 = (const float*)d_in[2];
    const float* b1 = (const float*)d_in[3];
    const float* W2 = (const float*)d_in[4];
    const float* b2 = (const float*)d_in[5];
    float* out = (float*)d_out;

    int n = in_sizes[0] / NFEAT;      // 100000
    int E = in_sizes[1] / 2;          // 1600000
    int nb = (n + 255) / 256;         // 391

    k_pre  <<<nb, 256>>>((const unsigned*)ei, n);
    k_hist <<<(E + 255) / 256, 256>>>(ei, E);
    k_scan <<<nb, 256>>>(n);
    k_csr  <<<(E + 255) / 256, 256>>>(E);

    k_gemm1<<<(n + 63) / 64, 256>>>(x, W1, b1, n);
    k_agg1 <<<(n * 32 + 255) / 256, 256>>>(n);

    k_gemm2<<<(n + 63) / 64, 160>>>(W2, b2, n);
    k_agg2 <<<(n * 32 + 255) / 256, 256>>>(out, n);
}